// round 17
// baseline (speedup 1.0000x reference)
#include <cuda_runtime.h>
#include <stdint.h>

// AND-tree over last dim of (ROWS, 1024) binary float matrix.
// out[row] = 1.0f iff all 1024 elements == 1.0f (bit pattern 0x3F800000).
//
// Final form. Coalesced warp-cooperative probing (R16 structure, best cold
// time of the session) with R=16 rows per warp: lane loads word `lane` of
// each of 16 consecutive rows -> 16 independent perfectly-coalesced LDG.32
// (MLP=16, 1 L1tex wavefront each), probing the full first 128B line of
// every row (survival 2^-32 -> ~zero survivors chip-wide). Survivor
// fallback: exact coalesced full-row recheck. 65536 mandatory line touches
// is the provable cold floor (each row's data is in disjoint lines); the
// timed path additionally sits on a fixed ~6.6us graph-replay overhead
// floor, invariant across all 9 measured kernel variants this session.

static constexpr int ROW_LEN = 1024;               // words per row
static constexpr unsigned ONE_BITS = 0x3F800000u;  // bit pattern of 1.0f
static constexpr int R = 16;                       // rows per warp
static constexpr int THREADS = 256;                // 8 warps per block

__global__ __launch_bounds__(THREADS) void vec_and_tree_kernel(
    const unsigned* __restrict__ x, float* __restrict__ out, int rows)
{
    const int warp_global = (blockIdx.x * THREADS + threadIdx.x) >> 5;
    const int lane = threadIdx.x & 31;
    const int base_row = warp_global * R;
    if (base_row >= rows) return;                  // rows % (R*warps/blk) == 0

    // Phase 1: R independent coalesced probes (first 128B line of each row),
    // all issued before any test -> MLP = R.
    unsigned v[R];
    #pragma unroll
    for (int k = 0; k < R; k++)
        v[k] = x[(size_t)(base_row + k) * ROW_LEN + lane];

    // Phase 2: one vote per row; 128B probe -> survival 2^-32 per row.
    unsigned m = 0;                                // warp-uniform result bitmask
    #pragma unroll
    for (int k = 0; k < R; k++) {
        bool ok = __all_sync(0xFFFFFFFFu, v[k] == ONE_BITS);
        if (ok) {
            // Essentially-never path: exact coalesced full-row recheck.
            const unsigned* rp = x + (size_t)(base_row + k) * ROW_LEN;
            bool lok = true;
            #pragma unroll 1
            for (int i = 1; i < ROW_LEN / 32; i++)
                lok &= (rp[i * 32 + lane] == ONE_BITS);
            ok = __all_sync(0xFFFFFFFFu, lok);
        }
        m |= (ok ? 1u : 0u) << k;
    }

    // Phase 3: coalesced output — lanes 0..R-1 write R consecutive rows.
    if (lane < R)
        out[base_row + lane] = (m >> lane) & 1u ? 1.0f : 0.0f;
}

extern "C" void kernel_launch(void* const* d_in, const int* in_sizes, int n_in,
                              void* d_out, int out_size)
{
    const unsigned* x = (const unsigned*)d_in[0];  // float32 bits reinterpreted
    float* out = (float*)d_out;

    const int rows = out_size;                     // 65536
    const int rows_per_block = (THREADS / 32) * R; // 128
    const int blocks = (rows + rows_per_block - 1) / rows_per_block;  // 512

    vec_and_tree_kernel<<<blocks, THREADS>>>(x, out, rows);
}